// round 2
// baseline (speedup 1.0000x reference)
#include <cuda_runtime.h>
#include <math_constants.h>

static constexpr int NPTS  = 4096;   // N source points
static constexpr int NUP   = 16384;  // upsampled points per batch
static constexpr int BATCH = 4;
static constexpr int C     = 64;     // channels == DIM
static constexpr int TPB   = 256;    // threads per block == queries per block

// smem: pos pair-SoA (NPTS/2 pairs * 2 float4) + W + b
static constexpr int SMEM_BYTES = NPTS * 16 + C * C * 4 + C * 4; // 82176

// ---- packed f32x2 helpers (Blackwell) ----
__device__ __forceinline__ unsigned long long pk2(float lo, float hi) {
    unsigned long long r;
    asm("mov.b64 %0, {%1, %2};" : "=l"(r) : "f"(lo), "f"(hi));
    return r;
}
__device__ __forceinline__ unsigned long long fma2(unsigned long long a,
                                                   unsigned long long b,
                                                   unsigned long long c) {
    unsigned long long d;
    asm("fma.rn.f32x2 %0, %1, %2, %3;" : "=l"(d) : "l"(a), "l"(b), "l"(c));
    return d;
}
__device__ __forceinline__ void unpk2(unsigned long long v, float& lo, float& hi) {
    asm("mov.b64 {%0, %1}, %2;" : "=f"(lo), "=f"(hi) : "l"(v));
}

__global__ void __launch_bounds__(TPB, 2)
up_kernel(const float* __restrict__ feature,
          const float* __restrict__ pos,
          const float* __restrict__ pos_up,
          const float* __restrict__ W,
          const float* __restrict__ bias,
          float* __restrict__ out)
{
    extern __shared__ float sm[];
    float4* spair = reinterpret_cast<float4*>(sm);  // [NPTS/2][2]: {x0,x1,y0,y1},{z0,z1,h0,h1}
    float*  sW    = sm + NPTS * 4;                  // [C*C]
    float*  sb    = sW + C * C;                     // [C]

    const int b   = blockIdx.y;
    const int tid = threadIdx.x;

    // ---- stage pos pairs (with half-norms), W, bias ----
    {
        const float* pb = pos + (size_t)b * NPTS * 3;
        for (int p = tid; p < NPTS / 2; p += TPB) {
            const float* s6 = pb + 6 * p;
            float x0 = s6[0], y0 = s6[1], z0 = s6[2];
            float x1 = s6[3], y1 = s6[4], z1 = s6[5];
            float h0 = 0.5f * (x0 * x0 + y0 * y0 + z0 * z0);
            float h1 = 0.5f * (x1 * x1 + y1 * y1 + z1 * z1);
            spair[2 * p + 0] = make_float4(x0, x1, y0, y1);
            spair[2 * p + 1] = make_float4(z0, z1, h0, h1);
        }
        for (int i = tid; i < C * C; i += TPB) sW[i] = W[i];
        if (tid < C) sb[tid] = bias[tid];
    }
    __syncthreads();

    // ---- per-query setup ----
    const int q = blockIdx.x * TPB + tid;
    const float* pu = pos_up + (size_t)(b * NUP + q) * 3;
    const float pux = pu[0], puy = pu[1], puz = pu[2];
    const float nu  = pux * pux + puy * puy + puz * puz;

    const unsigned long long nx2 = pk2(-pux, -pux);
    const unsigned long long ny2 = pk2(-puy, -puy);
    const unsigned long long nz2 = pk2(-puz, -puz);

    // ---- top-3 scan over point pairs (s = 0.5|p|^2 - pu.p, monotone in d^2) ----
    float v0 = CUDART_INF_F, v1 = CUDART_INF_F, v2 = CUDART_INF_F;
    int   i0 = 0, i1 = 0, i2 = 0;

    const float4* sp = spair;
    #pragma unroll 4
    for (int p = 0; p < NPTS / 2; ++p) {
        float4 A  = sp[2 * p + 0];   // x0,x1,y0,y1
        float4 Bv = sp[2 * p + 1];   // z0,z1,h0,h1
        unsigned long long xs = pk2(A.x, A.y);
        unsigned long long ys = pk2(A.z, A.w);
        unsigned long long zs = pk2(Bv.x, Bv.y);
        unsigned long long hs = pk2(Bv.z, Bv.w);
        unsigned long long sP = fma2(xs, nx2, hs);
        sP = fma2(ys, ny2, sP);
        sP = fma2(zs, nz2, sP);
        float s0, s1;
        unpk2(sP, s0, s1);

        if (fminf(s0, s1) < v2) {    // rare (≈32% of pair-iters per warp)
            if (s0 < v2) {
                if (s0 < v1) {
                    v2 = v1; i2 = i1;
                    if (s0 < v0) { v1 = v0; i1 = i0; v0 = s0; i0 = 2 * p; }
                    else         { v1 = s0; i1 = 2 * p; }
                } else { v2 = s0; i2 = 2 * p; }
            }
            if (s1 < v2) {
                if (s1 < v1) {
                    v2 = v1; i2 = i1;
                    if (s1 < v0) { v1 = v0; i1 = i0; v0 = s1; i0 = 2 * p + 1; }
                    else         { v1 = s1; i1 = 2 * p + 1; }
                } else { v2 = s1; i2 = 2 * p + 1; }
            }
        }
    }

    // ---- inverse-distance weights, normalized ----
    float w0 = 1.0f / (__fmaf_rn(2.0f, v0, nu) + 1e-6f);
    float w1 = 1.0f / (__fmaf_rn(2.0f, v1, nu) + 1e-6f);
    float w2 = 1.0f / (__fmaf_rn(2.0f, v2, nu) + 1e-6f);
    float inv = 1.0f / (w0 + w1 + w2);
    w0 *= inv; w1 *= inv; w2 *= inv;

    const float4* f0 = reinterpret_cast<const float4*>(feature + (size_t)(b * NPTS + i0) * C);
    const float4* f1 = reinterpret_cast<const float4*>(feature + (size_t)(b * NPTS + i1) * C);
    const float4* f2 = reinterpret_cast<const float4*>(feature + (size_t)(b * NPTS + i2) * C);

    // ---- fused interp + 64x64 GEMM + bias ----
    float acc[64];
    #pragma unroll
    for (int d = 0; d < 64; ++d) acc[d] = sb[d];

    for (int c4 = 0; c4 < 16; ++c4) {
        float4 a = __ldg(f0 + c4);
        float4 e = __ldg(f1 + c4);
        float4 g = __ldg(f2 + c4);
        float nf[4];
        nf[0] = __fmaf_rn(w0, a.x, __fmaf_rn(w1, e.x, w2 * g.x));
        nf[1] = __fmaf_rn(w0, a.y, __fmaf_rn(w1, e.y, w2 * g.y));
        nf[2] = __fmaf_rn(w0, a.z, __fmaf_rn(w1, e.z, w2 * g.z));
        nf[3] = __fmaf_rn(w0, a.w, __fmaf_rn(w1, e.w, w2 * g.w));

        const float4* wr = reinterpret_cast<const float4*>(sW + (size_t)c4 * 4 * C);
        #pragma unroll
        for (int k = 0; k < 4; ++k) {
            float nfc = nf[k];
            #pragma unroll
            for (int m = 0; m < 16; ++m) {
                float4 wv = wr[k * 16 + m];
                acc[4 * m + 0] = __fmaf_rn(nfc, wv.x, acc[4 * m + 0]);
                acc[4 * m + 1] = __fmaf_rn(nfc, wv.y, acc[4 * m + 1]);
                acc[4 * m + 2] = __fmaf_rn(nfc, wv.z, acc[4 * m + 2]);
                acc[4 * m + 3] = __fmaf_rn(nfc, wv.w, acc[4 * m + 3]);
            }
        }
    }

    // ---- ReLU + vectorized store ----
    float4* o4 = reinterpret_cast<float4*>(out + (size_t)(b * NUP + q) * C);
    #pragma unroll
    for (int m = 0; m < 16; ++m) {
        float4 v;
        v.x = fmaxf(acc[4 * m + 0], 0.0f);
        v.y = fmaxf(acc[4 * m + 1], 0.0f);
        v.z = fmaxf(acc[4 * m + 2], 0.0f);
        v.w = fmaxf(acc[4 * m + 3], 0.0f);
        o4[m] = v;
    }
}

extern "C" void kernel_launch(void* const* d_in, const int* in_sizes, int n_in,
                              void* d_out, int out_size)
{
    const float* feature = (const float*)d_in[0];
    const float* pos     = (const float*)d_in[1];
    const float* pos_up  = (const float*)d_in[2];
    const float* W       = (const float*)d_in[3];
    const float* bias    = (const float*)d_in[4];
    float* out = (float*)d_out;

    cudaFuncSetAttribute(up_kernel, cudaFuncAttributeMaxDynamicSharedMemorySize, SMEM_BYTES);

    dim3 grid(NUP / TPB, BATCH);
    up_kernel<<<grid, TPB, SMEM_BYTES>>>(feature, pos, pos_up, W, bias, out);
}